// round 17
// baseline (speedup 1.0000x reference)
#include <cuda_runtime.h>
#include <cuda_bf16.h>
#include <cstdint>

#define NN 50000
#define FD 128
#define ELLW 64                      // padded slots per node (1 + Poisson(16) << 64)

// ---------------- device scratch (no allocations allowed) ----------------
__device__ float g_hs[NN * FD];      // (X@W) * dinv[row]
__device__ float g_a[NN * FD];       // layer-1 activations
__device__ int   g_deg[NN];          // degree incl. self-loop
__device__ int   g_ell[NN * ELLW];   // ELL adjacency: row i = sources into i
__device__ int   g_is64;

// ---------------- detect edge dtype (int64 vs int32) + init ----------------
__global__ void detect_init_k(const int* __restrict__ ei, int n) {
    int i = blockIdx.x * blockDim.x + threadIdx.x;
    if (i < n) {
        g_deg[i] = 1;                // self-loop pre-counted
        g_ell[i * ELLW] = i;         // self-loop occupies slot 0
    }
    if (blockIdx.x == 0) {
        int w = ei[2 * threadIdx.x + 1];
        int any = __syncthreads_or(w != 0);
        if (threadIdx.x == 0) g_is64 = (any == 0) ? 1 : 0;
    }
}

// ---------------- ELL fill: atomic return IS the slot index -----------------
__global__ void fill_ell_k(const void* __restrict__ ei, int E) {
    int e = blockIdx.x * blockDim.x + threadIdx.x;
    if (e >= E) return;
    int s, d;
    if (g_is64) {
        const long long* p = (const long long*)ei;
        s = (int)p[e];
        d = (int)p[(long long)E + e];
    } else {
        const int* p = (const int*)ei;
        s = p[e];
        d = p[E + e];
    }
    int pos = atomicAdd(&g_deg[d], 1);
    if (pos < ELLW) g_ell[d * ELLW + pos] = s;
}

// ============================================================================
// Path A: tcgen05 GEMM — only compiled when an sm_103a pass exists.
// ============================================================================
#if defined(__CUDA_ARCH_FEAT_SM103_ALL)

__device__ __forceinline__ uint32_t smem_u32(const void* p) {
    uint32_t a;
    asm("{ .reg .u64 t; cvta.to.shared.u64 t, %1; cvt.u32.u64 %0, t; }"
        : "=r"(a) : "l"(p));
    return a;
}
__device__ __forceinline__ uint32_t elect_one() {
    uint32_t pred;
    asm volatile("{\n\t.reg .pred p;\n\telect.sync _|p, 0xFFFFFFFF;\n\t"
                 "selp.b32 %0, 1, 0, p;\n\t}" : "=r"(pred));
    return pred;
}
#define TC_ALLOC(sm, ncols) \
    asm volatile("tcgen05.alloc.cta_group::1.sync.aligned.shared::cta.b32 [%0], %1;" \
                 :: "r"(sm), "r"((uint32_t)(ncols)) : "memory")
#define TC_DEALLOC(tm, ncols) \
    asm volatile("tcgen05.dealloc.cta_group::1.sync.aligned.b32 %0, %1;" \
                 :: "r"(tm), "r"((uint32_t)(ncols)))
#define TC_COMMIT(mbar) \
    asm volatile("tcgen05.commit.cta_group::1.mbarrier::arrive::one.shared::cluster.b64 [%0];" \
                 :: "r"(mbar) : "memory")
#define MBAR_INIT(mbar, cnt) \
    asm volatile("mbarrier.init.shared.b64 [%0], %1;" :: "r"(mbar), "r"((uint32_t)(cnt)) : "memory")
#define MBAR_INVAL(mbar) \
    asm volatile("mbarrier.inval.shared.b64 [%0];" :: "r"(mbar) : "memory")
#define MBAR_WAIT(mbar, par) do {                                            \
    uint32_t _m = (mbar), _p = (par);                                        \
    asm volatile("{\n\t.reg .pred P1;\n\t"                                   \
        "WAIT_LOOP_%=:\n\t"                                                  \
        "mbarrier.try_wait.parity.acquire.cta.shared::cta.b64 P1, [%0], %1, 0x989680;\n\t" \
        "@P1 bra.uni WAIT_DONE_%=;\n\t"                                      \
        "bra.uni WAIT_LOOP_%=;\n\t"                                          \
        "WAIT_DONE_%=:\n\t}" :: "r"(_m), "r"(_p) : "memory");                \
} while (0)
#define TC_FENCE_AFTER()  asm volatile("tcgen05.fence::after_thread_sync;" ::: "memory")
#define TC_FENCE_BEFORE() asm volatile("tcgen05.fence::before_thread_sync;" ::: "memory")
#define TC_WAIT_LD()      asm volatile("tcgen05.wait::ld.sync.aligned;" ::: "memory")
#define FENCE_ASYNC()     asm volatile("fence.proxy.async.shared::cta;" ::: "memory")

__device__ __forceinline__ void tc_mma_f16_ss(uint32_t d, uint64_t ad, uint64_t bd,
                                              uint32_t idesc, uint32_t en) {
    asm volatile(
        "{\n\t.reg .pred p;\n\tsetp.ne.u32 p, %5, 0;\n\t"
        "tcgen05.mma.cta_group::1.kind::f16 [%0], %1, %2, %3, {%4, %4, %4, %4}, p;\n\t}"
        :: "r"(d), "l"(ad), "l"(bd), "r"(idesc), "r"(0u), "r"(en) : "memory");
}
__device__ __forceinline__ void tc_ld32(uint32_t* r, uint32_t tm) {
    asm volatile(
        "tcgen05.ld.sync.aligned.32x32b.x32.b32 "
        "{%0,%1,%2,%3,%4,%5,%6,%7,%8,%9,%10,%11,%12,%13,%14,%15,"
        "%16,%17,%18,%19,%20,%21,%22,%23,%24,%25,%26,%27,%28,%29,%30,%31}, [%32];"
        : "=r"(r[0]), "=r"(r[1]), "=r"(r[2]), "=r"(r[3]), "=r"(r[4]), "=r"(r[5]),
          "=r"(r[6]), "=r"(r[7]), "=r"(r[8]), "=r"(r[9]), "=r"(r[10]), "=r"(r[11]),
          "=r"(r[12]), "=r"(r[13]), "=r"(r[14]), "=r"(r[15]), "=r"(r[16]), "=r"(r[17]),
          "=r"(r[18]), "=r"(r[19]), "=r"(r[20]), "=r"(r[21]), "=r"(r[22]), "=r"(r[23]),
          "=r"(r[24]), "=r"(r[25]), "=r"(r[26]), "=r"(r[27]), "=r"(r[28]), "=r"(r[29]),
          "=r"(r[30]), "=r"(r[31])
        : "r"(tm));
}
__device__ __forceinline__ uint64_t make_desc(uint32_t addr) {
    return ((uint64_t)2 << 61) | ((uint64_t)1 << 46) | ((uint64_t)64 << 32)
         | ((uint64_t)1 << 16) | ((uint64_t)(addr >> 4) & 0x3FFF);
}
__device__ __forceinline__ uint32_t tile_off(int r, int c) {
    uint32_t off = (uint32_t)(((r >> 3) + ((c >> 6) << 4)) * 1024
                              + (r & 7) * 128 + (c & 63) * 2);
    return off ^ ((off >> 3) & 0x70);
}
#define MMA_IDESC (0x490u | (16u << 17) | (8u << 24))
#endif  // feature

// SMEM layout for the MMA kernel (dynamic, 132096 B)
#define SM_TMEMP 0
#define SM_MBAR  8
#define SM_AH    1024
#define SM_AL    33792
#define SM_BH    66560
#define SM_BL    99328
#define SM_TOTAL 132096
#define SM_STAGE 1024                // reuse A/B region post-MMA (f32[col][129])

// ---------------- tcgen05 GEMM kernel (empty body on sm_103 pass) -----------
__global__ void __launch_bounds__(256) mma_gemm_k(const float* __restrict__ Xext,
                                                  const float* __restrict__ W,
                                                  int use_internal, int n) {
#if defined(__CUDA_ARCH_FEAT_SM103_ALL)
    extern __shared__ char smem[];
    const float* __restrict__ X = use_internal ? g_a : Xext;
    uint32_t sb = smem_u32(smem);
    int tid = threadIdx.x;
    int wid = tid >> 5;
    int lane = tid & 31;
    int blockRow = blockIdx.x * 128;

    if (wid == 0) TC_ALLOC(sb + SM_TMEMP, 128);
    __syncthreads();
    uint32_t tmem;
    asm volatile("ld.shared.b32 %0, [%1];" : "=r"(tmem) : "r"(sb + SM_TMEMP));

    // X tile -> bf16 hi/lo, blocked SW128 layout
    for (int i = tid; i < 128 * 32; i += 256) {
        int m = i >> 5;
        int k = (i & 31) * 4;
        int row = blockRow + m;
        float4 v = make_float4(0.f, 0.f, 0.f, 0.f);
        if (row < n) v = *(const float4*)&X[row * FD + k];
        __nv_bfloat16 h0 = __float2bfloat16(v.x), h1 = __float2bfloat16(v.y);
        __nv_bfloat16 h2 = __float2bfloat16(v.z), h3 = __float2bfloat16(v.w);
        __nv_bfloat16 l0 = __float2bfloat16(v.x - __bfloat162float(h0));
        __nv_bfloat16 l1 = __float2bfloat16(v.y - __bfloat162float(h1));
        __nv_bfloat16 l2 = __float2bfloat16(v.z - __bfloat162float(h2));
        __nv_bfloat16 l3 = __float2bfloat16(v.w - __bfloat162float(h3));
        __nv_bfloat162 hp01(h0, h1), hp23(h2, h3), lp01(l0, l1), lp23(l2, l3);
        uint32_t o01 = tile_off(m, k), o23 = tile_off(m, k + 2);
        *(uint32_t*)(smem + SM_AH + o01) = *(uint32_t*)&hp01;
        *(uint32_t*)(smem + SM_AH + o23) = *(uint32_t*)&hp23;
        *(uint32_t*)(smem + SM_AL + o01) = *(uint32_t*)&lp01;
        *(uint32_t*)(smem + SM_AL + o23) = *(uint32_t*)&lp23;
    }
    // W -> transposed B tiles (B[n][k] = W[k][n]), hi/lo
    for (int i = tid; i < 128 * 32; i += 256) {
        int k = i >> 5;
        int n4 = (i & 31) * 4;
        float4 v = *(const float4*)&W[k * FD + n4];
#pragma unroll
        for (int j = 0; j < 4; j++) {
            float f = (j == 0) ? v.x : (j == 1) ? v.y : (j == 2) ? v.z : v.w;
            __nv_bfloat16 h = __float2bfloat16(f);
            __nv_bfloat16 l = __float2bfloat16(f - __bfloat162float(h));
            uint32_t o = tile_off(n4 + j, k);
            *(__nv_bfloat16*)(smem + SM_BH + o) = h;
            *(__nv_bfloat16*)(smem + SM_BL + o) = l;
        }
    }
    __syncthreads();

    if (wid == 0) {
        if (elect_one()) MBAR_INIT(sb + SM_MBAR, 1);
        __syncwarp();
        FENCE_ASYNC();
        uint64_t ah = make_desc(sb + SM_AH), al = make_desc(sb + SM_AL);
        uint64_t bh = make_desc(sb + SM_BH), bl = make_desc(sb + SM_BL);
        if (elect_one()) {
            uint64_t ad[3] = {ah, ah, al};
            uint64_t bd[3] = {bh, bl, bh};
#pragma unroll
            for (int pass = 0; pass < 3; pass++) {
#pragma unroll
                for (int k = 0; k < 8; k++) {
                    uint64_t koff = (uint64_t)((k >> 2) * 1024 + (k & 3) * 2);
                    tc_mma_f16_ss(tmem, ad[pass] + koff, bd[pass] + koff,
                                  MMA_IDESC, (pass | k) != 0);
                }
            }
            TC_COMMIT(sb + SM_MBAR);
        }
    }
    __syncthreads();
    MBAR_WAIT(sb + SM_MBAR, 0);
    TC_FENCE_AFTER();

    float* stage = (float*)(smem + SM_STAGE);   // stage[col*129 + row]
    {
        int wsub = wid & 3;
        int wcol = (wid >> 2) * 64;
        uint32_t regs[32];
#pragma unroll
        for (int half = 0; half < 2; half++) {
            int colb = wcol + half * 32;
            tc_ld32(regs, tmem + colb);
            TC_WAIT_LD();
#pragma unroll
            for (int c = 0; c < 32; c++)
                stage[(colb + c) * 129 + wsub * 32 + lane] = __uint_as_float(regs[c]);
        }
        TC_FENCE_BEFORE();
    }
    __syncthreads();
    if (wid == 0) {
        if (elect_one()) MBAR_INVAL(sb + SM_MBAR);
        TC_DEALLOC(tmem, 128);
    }
    for (int i = tid; i < 128 * 32; i += 256) {
        int r = i >> 5;
        int c4 = (i & 31) * 4;
        int grow = blockRow + r;
        if (grow < n) {
            float s = rsqrtf((float)g_deg[grow]);
            float4 o;
            o.x = stage[(c4 + 0) * 129 + r] * s;
            o.y = stage[(c4 + 1) * 129 + r] * s;
            o.z = stage[(c4 + 2) * 129 + r] * s;
            o.w = stage[(c4 + 3) * 129 + r] * s;
            *(float4*)&g_hs[grow * FD + c4] = o;
        }
    }
#endif  // feature — empty body on sm_103 pass
}

// ---------------- FFMA2 GEMM kernel (empty body on sm_103a pass) ------------
// [R12-winning form] BM=64, BN=128, BK=16; 256 thr; tile 8x4; fma.rn.f32x2.
__global__ void __launch_bounds__(256) gemm_k(const float* __restrict__ Xext,
                                              const float* __restrict__ W,
                                              int use_internal, int n) {
#if !defined(__CUDA_ARCH_FEAT_SM103_ALL)
    const float* __restrict__ X = use_internal ? g_a : Xext;
    __shared__ float Xs[16][68];
    __shared__ float Ws[16][128];

    int tid = threadIdx.x;
    int tx = tid & 31;
    int ty = tid >> 5;
    int blockRow = blockIdx.x * 64;

    unsigned long long acc[4][4];
#pragma unroll
    for (int p = 0; p < 4; p++)
#pragma unroll
        for (int c = 0; c < 4; c++) acc[p][c] = 0ull;

    for (int kt = 0; kt < FD; kt += 16) {
        {
            int r = tid >> 2;
            int cg = tid & 3;
            int row = blockRow + r;
            float4 v = make_float4(0.f, 0.f, 0.f, 0.f);
            if (row < n) v = *(const float4*)&X[row * FD + kt + cg * 4];
            Xs[cg * 4 + 0][r] = v.x;
            Xs[cg * 4 + 1][r] = v.y;
            Xs[cg * 4 + 2][r] = v.z;
            Xs[cg * 4 + 3][r] = v.w;
        }
        {
            int r = tid >> 5;
            int c4 = (tid & 31) * 4;
            *(float4*)&Ws[r][c4]     = *(const float4*)&W[(kt + r) * FD + c4];
            *(float4*)&Ws[r + 8][c4] = *(const float4*)&W[(kt + r + 8) * FD + c4];
        }
        __syncthreads();
#pragma unroll
        for (int kk = 0; kk < 16; kk++) {
            const ulonglong2* ap = (const ulonglong2*)&Xs[kk][ty * 8];
            ulonglong2 a01_23 = ap[0];
            ulonglong2 a45_67 = ap[1];
            unsigned long long apk[4] = {a01_23.x, a01_23.y, a45_67.x, a45_67.y};

            float4 bv = *(const float4*)&Ws[kk][tx * 4];
            unsigned long long bpk[4];
            asm("mov.b64 %0, {%1, %1};" : "=l"(bpk[0]) : "f"(bv.x));
            asm("mov.b64 %0, {%1, %1};" : "=l"(bpk[1]) : "f"(bv.y));
            asm("mov.b64 %0, {%1, %1};" : "=l"(bpk[2]) : "f"(bv.z));
            asm("mov.b64 %0, {%1, %1};" : "=l"(bpk[3]) : "f"(bv.w));

#pragma unroll
            for (int p = 0; p < 4; p++)
#pragma unroll
                for (int c = 0; c < 4; c++)
                    asm("fma.rn.f32x2 %0, %1, %2, %0;"
                        : "+l"(acc[p][c]) : "l"(apk[p]), "l"(bpk[c]));
        }
        __syncthreads();
    }

#pragma unroll
    for (int p = 0; p < 4; p++) {
        float2 u0 = *(float2*)&acc[p][0];
        float2 u1 = *(float2*)&acc[p][1];
        float2 u2 = *(float2*)&acc[p][2];
        float2 u3 = *(float2*)&acc[p][3];
        int row0 = blockRow + ty * 8 + 2 * p;
        if (row0 < n) {
            float s = rsqrtf((float)g_deg[row0]);
            *(float4*)&g_hs[row0 * FD + tx * 4] =
                make_float4(u0.x * s, u1.x * s, u2.x * s, u3.x * s);
        }
        int row1 = row0 + 1;
        if (row1 < n) {
            float s = rsqrtf((float)g_deg[row1]);
            *(float4*)&g_hs[row1 * FD + tx * 4] =
                make_float4(u0.y * s, u1.y * s, u2.y * s, u3.y * s);
        }
    }
#endif  // !feature — empty body on sm_103a pass
}

// ---------------- Aggregation over ELL rows (R12-winning form) --------------
// out[i] = rsqrt(deg[i]) * (sum_{slot<deg[i]} hs[ell[i][slot]]) + b
template <bool LAYER1>
__global__ void __launch_bounds__(256) agg_k(const float* __restrict__ bvec,
                                             float* __restrict__ out_ext, int n) {
    int node = blockIdx.x * (blockDim.x >> 5) + (threadIdx.x >> 5);
    if (node >= n) return;
    int lane = threadIdx.x & 31;

    const float4* __restrict__ hs = (const float4*)g_hs;
    const int* __restrict__ row = &g_ell[node * ELLW];
    int cnt = g_deg[node];
    if (cnt > ELLW) cnt = ELLW;

    float4 acc = make_float4(0.f, 0.f, 0.f, 0.f);
    int e = 0;
    for (; e + 3 < cnt; e += 4) {
        int j0 = row[e], j1 = row[e + 1], j2 = row[e + 2], j3 = row[e + 3];
        float4 v0 = hs[j0 * 32 + lane];
        float4 v1 = hs[j1 * 32 + lane];
        float4 v2 = hs[j2 * 32 + lane];
        float4 v3 = hs[j3 * 32 + lane];
        acc.x += (v0.x + v1.x) + (v2.x + v3.x);
        acc.y += (v0.y + v1.y) + (v2.y + v3.y);
        acc.z += (v0.z + v1.z) + (v2.z + v3.z);
        acc.w += (v0.w + v1.w) + (v2.w + v3.w);
    }
    for (; e < cnt; e++) {
        int j = row[e];
        float4 v = hs[j * 32 + lane];
        acc.x += v.x; acc.y += v.y; acc.z += v.z; acc.w += v.w;
    }

    float s = rsqrtf((float)g_deg[node]);
    float4 b = ((const float4*)bvec)[lane];
    float4 r;
    r.x = fmaf(acc.x, s, b.x);
    r.y = fmaf(acc.y, s, b.y);
    r.z = fmaf(acc.z, s, b.z);
    r.w = fmaf(acc.w, s, b.w);
    if (LAYER1) {
        r.x = fmaxf(r.x, 0.f); r.y = fmaxf(r.y, 0.f);
        r.z = fmaxf(r.z, 0.f); r.w = fmaxf(r.w, 0.f);
        ((float4*)g_a)[node * 32 + lane] = r;
    } else {
        ((float4*)out_ext)[node * 32 + lane] = r;
    }
}

// ---------------- launch ----------------
extern "C" void kernel_launch(void* const* d_in, const int* in_sizes, int n_in,
                              void* d_out, int out_size) {
    const float* x  = (const float*)d_in[0];
    const void*  ei = d_in[1];
    const float* W1 = (const float*)d_in[2];
    const float* b1 = (const float*)d_in[3];
    const float* W2 = (const float*)d_in[4];
    const float* b2 = (const float*)d_in[5];

    int n = in_sizes[0] / FD;      // 50000
    int E = in_sizes[1] / 2;       // 800000

    static int smem_set = 0;
    if (!smem_set) {
        cudaFuncSetAttribute(mma_gemm_k,
                             cudaFuncAttributeMaxDynamicSharedMemorySize, SM_TOTAL);
        smem_set = 1;
    }

    int mma_blocks  = (n + 127) / 128;         // 391
    int gemm_blocks = (n + 63) / 64;           // 782
    int agg_blocks  = (n + 7) / 8;             // 6250

    detect_init_k<<<(n + 1023) / 1024, 1024>>>((const int*)ei, n);
    fill_ell_k<<<(E + 255) / 256, 256>>>(ei, E);

    // Layer 1 GEMM: exactly one of these has a non-empty body per arch pass.
    mma_gemm_k<<<mma_blocks, 256, SM_TOTAL>>>(x, W1, 0, n);
    gemm_k<<<gemm_blocks, 256>>>(x, W1, 0, n);
    agg_k<true><<<agg_blocks, 256>>>(b1, (float*)d_out, n);   // g_a = relu(...)

    // Layer 2 GEMM
    mma_gemm_k<<<mma_blocks, 256, SM_TOTAL>>>(nullptr, W2, 1, n);
    gemm_k<<<gemm_blocks, 256>>>(nullptr, W2, 1, n);
    agg_k<false><<<agg_blocks, 256>>>(b2, (float*)d_out, n);  // d_out = final
}